// round 12
// baseline (speedup 1.0000x reference)
#include <cuda_runtime.h>
#include <cuda_bf16.h>
#include <cstdint>

// out[i,j] = sigmoid( sum_h W2[h]*relu(A[i,h]+B[j,h]) + b2 )
//   A = Z@W1[:D] + b1, B = Z@W1[D:].
// Two-form split to balance alu/fma pipes:
//  h <  HM (max-form): w*relu(a+b) = w*max(a,-b) + w*b      (FMNMX alu + FFMA2 fma)
//  h >= HM (abs-form): w*relu(s) = 0.5w*s + 0.5w*|s|, s=a+b (FADD + FFMA, both fma;
//                      the 0.5w*s part telescopes into per-i/per-j constants)
// logits = accM + accA + K_i + L_j + b2
//   K_i = 0.5*sum_{h>=HM} w_h A[i,h]
//   L_j = sum_{h<HM} w_h B[j,h] + 0.5*sum_{h>=HM} w_h B[j,h]
#define NN 2048
#define DD 32
#define HH 64
#define HM 52

__device__ float g_A [NN * HH];  // A[n][h]
__device__ float g_nB[NN * HH];  // -B[n][h]
__device__ float g_K [NN];       // per-i constant
__device__ float g_L [NN];       // per-j constant
__device__ int   g_ctr;          // work-stealing tile counter

typedef unsigned long long u64t;

// max-form: acc(f32x2) += max2(a, nb) * w.  2x FMNMX (alu) + 1x FFMA2 (fma).
__device__ __forceinline__ void max_fma2(u64t& acc, float ax, float ay,
                                         float bx, float by, u64t w) {
    asm("{\n\t"
        ".reg .f32 lo, hi;\n\t"
        ".reg .b64 t;\n\t"
        "max.f32 lo, %1, %3;\n\t"
        "max.f32 hi, %2, %4;\n\t"
        "mov.b64 t, {lo, hi};\n\t"
        "fma.rn.f32x2 %0, t, %5, %0;\n\t"
        "}" : "+l"(acc) : "f"(ax), "f"(ay), "f"(bx), "f"(by), "l"(w));
}

// abs-form: acc.lo += |ax - nbx| * wx ; acc.hi += |ay - nby| * wy
// (s = a - (-b) = a + b; abs folds into the FFMA source modifier)
__device__ __forceinline__ void abs_fma2(u64t& acc, float ax, float ay,
                                         float nbx, float nby,
                                         float wx, float wy) {
    asm("{\n\t"
        ".reg .f32 lo, hi, s0, s1;\n\t"
        "mov.b64 {lo, hi}, %0;\n\t"
        "sub.f32 s0, %1, %3;\n\t"
        "sub.f32 s1, %2, %4;\n\t"
        "abs.f32 s0, s0;\n\t"
        "abs.f32 s1, s1;\n\t"
        "fma.rn.f32 lo, s0, %5, lo;\n\t"
        "fma.rn.f32 hi, s1, %6, hi;\n\t"
        "mov.b64 %0, {lo, hi};\n\t"
        "}" : "+l"(acc) : "f"(ax), "f"(ay), "f"(nbx), "f"(nby), "f"(wx), "f"(wy));
}

__device__ __forceinline__ void cp8(float* s, const float* g) {
    unsigned int sa = (unsigned int)__cvta_generic_to_shared(s);
    asm volatile("cp.async.ca.shared.global [%0], [%1], 8;" :: "r"(sa), "l"(g));
}

#define GRID 444   // 3 CTAs/SM x 148 SMs

// ---------------------------------------------------------------------------
// Prep: A, -B, K, L, reset work counter. 512 blocks x 256 threads.
// ---------------------------------------------------------------------------
__global__ void prep_kernel(const float* __restrict__ Z,
                            const float* __restrict__ W1,
                            const float* __restrict__ b1,
                            const float* __restrict__ W2) {
    __shared__ float zs[4][DD];
    __shared__ float cbufK[4][HH];
    __shared__ float cbufL[4][HH];
    int tid = threadIdx.x;
    int nblk = blockIdx.x * 4;
    if (blockIdx.x == 0 && tid == 0) g_ctr = GRID;
    if (tid < 4 * DD) {
        zs[tid >> 5][tid & 31] = Z[(nblk + (tid >> 5)) * DD + (tid & 31)];
    }
    __syncthreads();
    int local_n = tid >> 6;
    int h = tid & 63;
    int n = nblk + local_n;
    float sa = b1[h];
    float sb = 0.0f;
#pragma unroll
    for (int d = 0; d < DD; d++) {
        float z = zs[local_n][d];
        sa = fmaf(z, W1[d * HH + h], sa);
        sb = fmaf(z, W1[(DD + d) * HH + h], sb);
    }
    g_A [n * HH + h] = sa;
    g_nB[n * HH + h] = -sb;
    float w = W2[h];
    cbufK[local_n][h] = (h >= HM) ? 0.5f * w * sa : 0.0f;
    cbufL[local_n][h] = ((h < HM) ? w : 0.5f * w) * sb;
    __syncthreads();
    if (tid < 4) {
        float ck = 0.0f, cl = 0.0f;
#pragma unroll
        for (int k = 0; k < HH; k++) { ck += cbufK[tid][k]; cl += cbufL[tid][k]; }
        g_K[nblk + tid] = ck;
        g_L[nblk + tid] = cl;
    }
}

// ---------------------------------------------------------------------------
// Persistent pair kernel: 3 CTAs/SM, work-stealing, cp.async double-buffered
// staging, register-pipelined math, two-form pipe-balanced inner loop.
// 64x64 tile, 4x4 pairs/thread, interleaved lanes, conflict-free LDS.64.
// ---------------------------------------------------------------------------
#define SROW 66
#define ABUF (64 * SROW)
#define NTILES 1024

__device__ __forceinline__ float sigmoid_fast(float x) {
    float t;
    asm("tanh.approx.f32 %0, %1;" : "=f"(t) : "f"(0.5f * x));
    return fmaf(0.5f, t, 0.5f);
}

__global__ __launch_bounds__(256, 3)
void pair_kernel(const float* __restrict__ W2,
                 const float* __restrict__ b2,
                 float* __restrict__ out) {
    extern __shared__ float smem[];
    // layout: As[2] | Bs[2] | ws(68) | next_t
    float* ws = smem + 4 * ABUF;
    int* next_s = (int*)(ws + 68);

    int tid = threadIdx.x;
    int tx = tid & 15;   // j lane
    int ty = tid >> 4;   // i lane
    float bias = b2[0];

    // abs-range weights pre-scaled by 0.5
    if (tid < HH) ws[tid] = W2[tid] * ((tid >= HM) ? 0.5f : 1.0f);
    if (tid >= 64 && tid < 68) ws[tid] = 0.0f;   // pad for wrapped prefetch

    int r0 = tid >> 5;            // 0..7
    int h2 = (tid & 31) * 2;      // word offset of 8B chunk

    int t = blockIdx.x;
    int p = 0;
    {   // Prologue: stage tile t into buffer 0
        int bj = (t & 31) * 64, bi = (t >> 5) * 64;
        const float* gA = g_A  + (bi + r0) * HH + h2;
        const float* gB = g_nB + (bj + r0) * HH + h2;
        float* sA = smem + r0 * SROW + h2;
        float* sB = smem + 2 * ABUF + r0 * SROW + h2;
#pragma unroll
        for (int c = 0; c < 8; c++) {
            cp8(sA + c * 8 * SROW, gA + c * 8 * HH);
            cp8(sB + c * 8 * SROW, gB + c * 8 * HH);
        }
        asm volatile("cp.async.commit_group;");
    }

    while (true) {
        if (tid == 0) *next_s = atomicAdd(&g_ctr, 1);
        __syncthreads();
        int tn = *next_s;
        if (tn < NTILES) {
            int bj = (tn & 31) * 64, bi = (tn >> 5) * 64;
            const float* gA = g_A  + (bi + r0) * HH + h2;
            const float* gB = g_nB + (bj + r0) * HH + h2;
            float* sA = smem + (p ^ 1) * ABUF + r0 * SROW + h2;
            float* sB = smem + (2 + (p ^ 1)) * ABUF + r0 * SROW + h2;
#pragma unroll
            for (int c = 0; c < 8; c++) {
                cp8(sA + c * 8 * SROW, gA + c * 8 * HH);
                cp8(sB + c * 8 * SROW, gB + c * 8 * HH);
            }
        }
        asm volatile("cp.async.commit_group;");
        asm volatile("cp.async.wait_group 1;");
        __syncthreads();

        int bj = (t & 31) * 64, bi = (t >> 5) * 64;
        const float* arow0 = smem + p * ABUF + ty * SROW;
        const float* brow0 = smem + (2 + p) * ABUF + tx * SROW;

        u64t acc[4][4];
#pragma unroll
        for (int ii = 0; ii < 4; ii++)
#pragma unroll
            for (int jj = 0; jj < 4; jj++) acc[ii][jj] = 0ull;

        // ---- max-form, h = 0..50, register-pipelined ----
        float2 ax[4], bx[4];  u64t wx;
        float2 ay[4], by[4];  u64t wy;
        wx = *(const u64t*)&ws[0];
#pragma unroll
        for (int ii = 0; ii < 4; ii++) ax[ii] = *(const float2*)&arow0[ii * 16 * SROW];
#pragma unroll
        for (int jj = 0; jj < 4; jj++) bx[jj] = *(const float2*)&brow0[jj * 16 * SROW];

#pragma unroll 2
        for (int hb = 0; hb < 48; hb += 4) {
            wy = *(const u64t*)&ws[hb + 2];
#pragma unroll
            for (int ii = 0; ii < 4; ii++)
                ay[ii] = *(const float2*)&arow0[ii * 16 * SROW + hb + 2];
#pragma unroll
            for (int jj = 0; jj < 4; jj++)
                by[jj] = *(const float2*)&brow0[jj * 16 * SROW + hb + 2];
#pragma unroll
            for (int jj = 0; jj < 4; jj++)
#pragma unroll
                for (int ii = 0; ii < 4; ii++)
                    max_fma2(acc[ii][jj], ax[ii].x, ax[ii].y, bx[jj].x, bx[jj].y, wx);
            wx = *(const u64t*)&ws[hb + 4];
#pragma unroll
            for (int ii = 0; ii < 4; ii++)
                ax[ii] = *(const float2*)&arow0[ii * 16 * SROW + hb + 4];
#pragma unroll
            for (int jj = 0; jj < 4; jj++)
                bx[jj] = *(const float2*)&brow0[jj * 16 * SROW + hb + 4];
#pragma unroll
            for (int jj = 0; jj < 4; jj++)
#pragma unroll
                for (int ii = 0; ii < 4; ii++)
                    max_fma2(acc[ii][jj], ay[ii].x, ay[ii].y, by[jj].x, by[jj].y, wy);
        }
        // boundary: X holds h=48; compute X(48), Y(50)
        {
            wy = *(const u64t*)&ws[50];
#pragma unroll
            for (int ii = 0; ii < 4; ii++)
                ay[ii] = *(const float2*)&arow0[ii * 16 * SROW + 50];
#pragma unroll
            for (int jj = 0; jj < 4; jj++)
                by[jj] = *(const float2*)&brow0[jj * 16 * SROW + 50];
#pragma unroll
            for (int jj = 0; jj < 4; jj++)
#pragma unroll
                for (int ii = 0; ii < 4; ii++)
                    max_fma2(acc[ii][jj], ax[ii].x, ax[ii].y, bx[jj].x, bx[jj].y, wx);
#pragma unroll
            for (int jj = 0; jj < 4; jj++)
#pragma unroll
                for (int ii = 0; ii < 4; ii++)
                    max_fma2(acc[ii][jj], ay[ii].x, ay[ii].y, by[jj].x, by[jj].y, wy);
        }

        // ---- abs-form, h = 52..62 (fma-pipe only; ws already holds 0.5w) ----
#pragma unroll
        for (int h = HM; h < HH; h += 2) {
            float2 wv = *(const float2*)&ws[h];
            float2 a2[4], nb2[4];
#pragma unroll
            for (int ii = 0; ii < 4; ii++)
                a2[ii] = *(const float2*)&arow0[ii * 16 * SROW + h];
#pragma unroll
            for (int jj = 0; jj < 4; jj++)
                nb2[jj] = *(const float2*)&brow0[jj * 16 * SROW + h];
#pragma unroll
            for (int jj = 0; jj < 4; jj++)
#pragma unroll
                for (int ii = 0; ii < 4; ii++)
                    abs_fma2(acc[ii][jj], a2[ii].x, a2[ii].y,
                             nb2[jj].x, nb2[jj].y, wv.x, wv.y);
        }

        // ---- epilogue ----
        float Lv[4];
#pragma unroll
        for (int jj = 0; jj < 4; jj++) Lv[jj] = __ldg(&g_L[bj + tx + jj * 16]);
#pragma unroll
        for (int ii = 0; ii < 4; ii++) {
            int gi = bi + ty + ii * 16;
            float Kv = __ldg(&g_K[gi]);
#pragma unroll
            for (int jj = 0; jj < 4; jj++) {
                int gj = bj + tx + jj * 16;
                float2 v = *(float2*)&acc[ii][jj];
                float x = v.x + v.y + Kv + Lv[jj] + bias;
                out[gi * NN + gj] = sigmoid_fast(x);
            }
        }

        if (tn >= NTILES) break;
        t = tn;
        p ^= 1;
    }
}

extern "C" void kernel_launch(void* const* d_in, const int* in_sizes, int n_in,
                              void* d_out, int out_size) {
    const float* Z  = (const float*)d_in[0];
    const float* W1 = (const float*)d_in[1];
    const float* b1 = (const float*)d_in[2];
    const float* W2 = (const float*)d_in[3];
    const float* b2 = (const float*)d_in[4];
    float* out = (float*)d_out;

    static const size_t SMEM_BYTES = (4 * ABUF + 68 + 4) * sizeof(float);
    cudaFuncSetAttribute(pair_kernel,
                         cudaFuncAttributeMaxDynamicSharedMemorySize,
                         (int)SMEM_BYTES);

    prep_kernel<<<NN / 4, 256>>>(Z, W1, b1, W2);
    pair_kernel<<<GRID, 256, SMEM_BYTES>>>(W2, b2, out);
}

// round 13
// speedup vs baseline: 1.4890x; 1.4890x over previous
#include <cuda_runtime.h>
#include <cuda_fp16.h>
#include <cstdint>

// out[i,j] = sigmoid( sum_h W2[h]*relu(A[i,h]+B[j,h]) + b2 )
//   A = Z@W1[:D] + b1, B = Z@W1[D:].
// Identity: relu(a+b) = max(a,-b)+b  =>  logits = sum_h w*max(a,-b) + C_j + b2.
// The N^2-scale sum runs in packed f16x2 (HMNMX2 + HFMA2, 1 slot/pair-h);
// the C_j correction and final reduction stay fp32. Two half2 accumulators
// per pair (h<32 / h>=32) bound fp16 accumulation error.
#define NN 2048
#define DD 32
#define HH 64

__device__ __half g_Ah [NN * HH];  // A[n][h]   (fp16)
__device__ __half g_nBh[NN * HH];  // -B[n][h]  (fp16)
__device__ float  g_C  [NN];       // C[j] = sum_h W2[h]*B[j,h]  (fp32)
__device__ int    g_ctr;           // work-stealing tile counter

// acc(h2) += max.f16x2(a,b) * w  twice (two h-pairs), serial acc chain len 2.
// 2x HMNMX2 (alu) + 2x HFMA2 (fma) per 4 pair-h.
__device__ __forceinline__ void hmax_fma(unsigned& acc,
                                         unsigned alo, unsigned ahi,
                                         unsigned blo, unsigned bhi,
                                         unsigned wlo, unsigned whi) {
    asm("{\n\t"
        ".reg .b32 t0, t1;\n\t"
        "max.f16x2 t0, %1, %3;\n\t"
        "max.f16x2 t1, %2, %4;\n\t"
        "fma.rn.f16x2 %0, t0, %5, %0;\n\t"
        "fma.rn.f16x2 %0, t1, %6, %0;\n\t"
        "}" : "+r"(acc)
            : "r"(alo), "r"(ahi), "r"(blo), "r"(bhi), "r"(wlo), "r"(whi));
}

__device__ __forceinline__ void cp8(void* s, const void* g) {
    unsigned int sa = (unsigned int)__cvta_generic_to_shared(s);
    asm volatile("cp.async.ca.shared.global [%0], [%1], 8;" :: "r"(sa), "l"(g));
}

#define GRID 444   // 3 CTAs/SM x 148 SMs

// ---------------------------------------------------------------------------
// Prep: fp16 A and -B, fp32 C, reset counter. 512 blocks x 256 threads.
// ---------------------------------------------------------------------------
__global__ void prep_kernel(const float* __restrict__ Z,
                            const float* __restrict__ W1,
                            const float* __restrict__ b1,
                            const float* __restrict__ W2) {
    __shared__ float zs[4][DD];
    __shared__ float cbuf[4][HH];
    int tid = threadIdx.x;
    int nblk = blockIdx.x * 4;
    if (blockIdx.x == 0 && tid == 0) g_ctr = GRID;
    if (tid < 4 * DD) {
        zs[tid >> 5][tid & 31] = Z[(nblk + (tid >> 5)) * DD + (tid & 31)];
    }
    __syncthreads();
    int local_n = tid >> 6;
    int h = tid & 63;
    int n = nblk + local_n;
    float sa = b1[h];
    float sb = 0.0f;
#pragma unroll
    for (int d = 0; d < DD; d++) {
        float z = zs[local_n][d];
        sa = fmaf(z, W1[d * HH + h], sa);
        sb = fmaf(z, W1[(DD + d) * HH + h], sb);
    }
    g_Ah [n * HH + h] = __float2half_rn(sa);
    g_nBh[n * HH + h] = __float2half_rn(-sb);
    cbuf[local_n][h] = sb * W2[h];     // fp32 correction term
    __syncthreads();
    if (tid < 4) {
        float c = 0.0f;
#pragma unroll
        for (int k = 0; k < HH; k++) c += cbuf[tid][k];
        g_C[nblk + tid] = c;
    }
}

// ---------------------------------------------------------------------------
// Persistent pair kernel: 3 CTAs/SM, work-stealing, cp.async double-buffered
// half-precision tiles, register-pipelined packed-fp16 inner loop.
// 64x64 tile, 4x4 pairs/thread, interleaved lanes (i=ty+16*ii, j=tx+16*jj).
// SROWH=68 halves (136B): conflict-free 8B loads, 8B-aligned rows.
// ---------------------------------------------------------------------------
#define SROWH 68
#define HBUF (64 * SROWH)
#define NTILES 1024

__device__ __forceinline__ float sigmoid_fast(float x) {
    float t;
    asm("tanh.approx.f32 %0, %1;" : "=f"(t) : "f"(0.5f * x));
    return fmaf(0.5f, t, 0.5f);
}

__global__ __launch_bounds__(256, 3)
void pair_kernel(const float* __restrict__ W2,
                 const float* __restrict__ b2,
                 float* __restrict__ out) {
    extern __shared__ __half hs[];
    // layout (halves): A0 | A1 | B0 | B1 | ws(72) | next_t(int)
    __half* ws = hs + 4 * HBUF;
    int* next_s = (int*)(ws + 72);

    int tid = threadIdx.x;
    int tx = tid & 15;   // j lane
    int ty = tid >> 4;   // i lane
    float bias = b2[0];

    if (tid < HH) ws[tid] = __float2half_rn(W2[tid]);
    if (tid >= 64 && tid < 72) ws[tid] = __ushort_as_half((unsigned short)0);

    int t = blockIdx.x;
    int p = 0;
    {   // Prologue: stage tile t into buffer 0 (A rows 128B -> 16 8B chunks)
        int bj = (t & 31) * 64, bi = (t >> 5) * 64;
        const __half* gA = g_Ah  + bi * HH;
        const __half* gB = g_nBh + bj * HH;
        for (int k = tid; k < 1024; k += 256) {
            int row = k >> 4, ch = (k & 15) * 4;
            cp8(hs + row * SROWH + ch,            gA + row * HH + ch);
            cp8(hs + 2 * HBUF + row * SROWH + ch, gB + row * HH + ch);
        }
        asm volatile("cp.async.commit_group;");
    }

    while (true) {
        if (tid == 0) *next_s = atomicAdd(&g_ctr, 1);
        __syncthreads();               // prev compute on buf p^1 done; next_s visible
        int tn = *next_s;
        if (tn < NTILES) {
            int bj = (tn & 31) * 64, bi = (tn >> 5) * 64;
            const __half* gA = g_Ah  + bi * HH;
            const __half* gB = g_nBh + bj * HH;
            __half* sA = hs + (p ^ 1) * HBUF;
            __half* sB = hs + (2 + (p ^ 1)) * HBUF;
            for (int k = tid; k < 1024; k += 256) {
                int row = k >> 4, ch = (k & 15) * 4;
                cp8(sA + row * SROWH + ch, gA + row * HH + ch);
                cp8(sB + row * SROWH + ch, gB + row * HH + ch);
            }
        }
        asm volatile("cp.async.commit_group;");
        asm volatile("cp.async.wait_group 1;");   // buf p arrived
        __syncthreads();

        int bj = (t & 31) * 64, bi = (t >> 5) * 64;
        const __half* ar = hs + p * HBUF + ty * SROWH;
        const __half* br = hs + (2 + p) * HBUF + tx * SROWH;

        // two half2 accumulators per pair: window 0 (h<32), window 1 (h>=32)
        unsigned acc[2][4][4];
#pragma unroll
        for (int w = 0; w < 2; w++)
#pragma unroll
            for (int ii = 0; ii < 4; ii++)
#pragma unroll
                for (int jj = 0; jj < 4; jj++) acc[w][ii][jj] = 0u;

        // register ping-pong over 16 steps of 4h (fully unrolled so the
        // acc-window select is compile-time)
        uint2 ax[4], bx[4], wx;
        uint2 ay[4], by[4], wy;

#define LOADB(AV, BV, WV, h)                                                   \
        do {                                                                   \
            WV = *(const uint2*)(ws + (h));                                    \
            _Pragma("unroll")                                                  \
            for (int ii = 0; ii < 4; ii++)                                     \
                AV[ii] = *(const uint2*)(ar + ii * 16 * SROWH + (h));          \
            _Pragma("unroll")                                                  \
            for (int jj = 0; jj < 4; jj++)                                     \
                BV[jj] = *(const uint2*)(br + jj * 16 * SROWH + (h));          \
        } while (0)

#define COMPB(AV, BV, WV, wsel)                                                \
        do {                                                                   \
            _Pragma("unroll")                                                  \
            for (int jj = 0; jj < 4; jj++)                                     \
                _Pragma("unroll")                                              \
                for (int ii = 0; ii < 4; ii++)                                 \
                    hmax_fma(acc[wsel][ii][jj], AV[ii].x, AV[ii].y,            \
                             BV[jj].x, BV[jj].y, WV.x, WV.y);                  \
        } while (0)

        LOADB(ax, bx, wx, 0);
#pragma unroll
        for (int hb = 0; hb < 64; hb += 8) {
            LOADB(ay, by, wy, hb + 4);
            COMPB(ax, bx, wx, (hb >= 32) ? 1 : 0);
            LOADB(ax, bx, wx, hb + 8);   // hb=56 loads pad (ws/rows padded; dead)
            COMPB(ay, by, wy, ((hb + 4) >= 32) ? 1 : 0);
        }
#undef LOADB
#undef COMPB

        // epilogue: fp32 reduce + fp32 correction + sigmoid
#pragma unroll
        for (int ii = 0; ii < 4; ii++) {
            int gi = bi + ty + ii * 16;
#pragma unroll
            for (int jj = 0; jj < 4; jj++) {
                int gj = bj + tx + jj * 16;
                float2 u = __half22float2(*(const half2*)&acc[0][ii][jj]);
                float2 v = __half22float2(*(const half2*)&acc[1][ii][jj]);
                float x = (u.x + u.y) + (v.x + v.y) + __ldg(&g_C[gj]) + bias;
                out[gi * NN + gj] = sigmoid_fast(x);   // coalesced across tx
            }
        }

        if (tn >= NTILES) break;
        t = tn;
        p ^= 1;
    }
}

extern "C" void kernel_launch(void* const* d_in, const int* in_sizes, int n_in,
                              void* d_out, int out_size) {
    const float* Z  = (const float*)d_in[0];
    const float* W1 = (const float*)d_in[1];
    const float* b1 = (const float*)d_in[2];
    const float* W2 = (const float*)d_in[3];
    const float* b2 = (const float*)d_in[4];
    float* out = (float*)d_out;

    static const size_t SMEM_BYTES = (4 * HBUF + 72) * sizeof(__half) + 8;
    cudaFuncSetAttribute(pair_kernel,
                         cudaFuncAttributeMaxDynamicSharedMemorySize,
                         (int)SMEM_BYTES);

    prep_kernel<<<NN / 4, 256>>>(Z, W1, b1, W2);
    pair_kernel<<<GRID, 256, SMEM_BYTES>>>(W2, b2, out);
}